// round 2
// baseline (speedup 1.0000x reference)
#include <cuda_runtime.h>

#define NTHREADS 512
#define TLEN 4096

struct __align__(16) Smem {
    float2 buf0[TLEN];     // FFT ping
    float2 buf1[TLEN];     // FFT pong
    float2 xsave[TLEN];    // saved forward spectrum X
    float2 tw[3072];       // twiddles exp(-2*pi*i*j/4096), j<3072
    float  modes[3][TLEN]; // 3 merged filtered modes (real)
    int    hist[16][36];   // per-warp transition histograms
    float  red[16][20];    // per-warp partial sums for corr (5 S + 15 Q)
    float  totals[20];
    int    cnt[36];
    float  xnyq;           // Re(X[2048])
};

__device__ __forceinline__ float2 cadd(float2 a, float2 b){ return make_float2(a.x+b.x, a.y+b.y); }
__device__ __forceinline__ float2 csub(float2 a, float2 b){ return make_float2(a.x-b.x, a.y-b.y); }
__device__ __forceinline__ float2 cmul(float2 a, float2 b){
    return make_float2(fmaf(a.x,b.x,-a.y*b.y), fmaf(a.x,b.y, a.y*b.x));
}

// Stockham autosort radix-4 DIF FFT, 4096 points, 6 stages. Result lands in b0,
// natural order. INV=true conjugates twiddles (unscaled inverse).
template<bool INV>
__device__ void fft4096(float2* __restrict__ b0, float2* __restrict__ b1,
                        const float2* __restrict__ tw, int tid)
{
    float2* src = b0;
    float2* dst = b1;
    #pragma unroll
    for (int stage = 0; stage < 6; ++stage) {
        const int slog = 2*stage;            // s = 4^stage
        #pragma unroll
        for (int it = 0; it < 2; ++it) {
            const int idx = tid + (it << 9); // 0..1023 butterflies
            const int p = idx >> slog;
            const int q = idx & ((1 << slog) - 1);
            float2 a = src[idx];
            float2 b = src[idx + 1024];
            float2 c = src[idx + 2048];
            float2 d = src[idx + 3072];
            const int ti = p << slog;        // <= 1023
            float2 w1 = tw[ti];
            float2 w2 = tw[2*ti];
            float2 w3 = tw[3*ti];
            if (INV) { w1.y = -w1.y; w2.y = -w2.y; w3.y = -w3.y; }
            float2 apc = cadd(a, c), amc = csub(a, c);
            float2 bpd = cadd(b, d), bmd = csub(b, d);
            float2 jb  = make_float2(-bmd.y, bmd.x);   // i*(b-d)
            float2 y0 = cadd(apc, bpd);
            float2 y2 = cmul(w2, csub(apc, bpd));
            float2 t1 = INV ? cadd(amc, jb) : csub(amc, jb);
            float2 t3 = INV ? csub(amc, jb) : cadd(amc, jb);
            float2 y1 = cmul(w1, t1);
            float2 y3 = cmul(w3, t3);
            const int sstep = 1 << slog;
            const int ob = q + ((p << slog) << 2);     // q + s*4p
            dst[ob]           = y0;
            dst[ob +   sstep] = y1;
            dst[ob + 2*sstep] = y2;
            dst[ob + 3*sstep] = y3;
        }
        __syncthreads();
        float2* t = src; src = dst; dst = t;
    }
}

// Lehmer code of stable argsort of (a,b,c), matching reference id formula.
__device__ __forceinline__ int permid(float a, float b, float c)
{
    int i0 = (a <= b) ? 1 : 0;
    int i1 = (a <= c) ? 1 : 0;
    int i2 = (b <= c) ? 1 : 0;
    int idx = (i0 << 2) | (i1 << 1) | i2;
    const unsigned LUT = (5u<<0)|(3u<<4)|(0u<<8)|(2u<<12)|(4u<<16)|(0u<<20)|(1u<<24)|(0u<<28);
    return (int)((LUT >> (idx*4)) & 0xFu);
}

__device__ __forceinline__ float gmask(float u) { return expf(-12.5f * u * u); }

// Q index for pair (k,l), k<=l, 5x5 upper triangle
__device__ __forceinline__ constexpr int qidx(int k, int l) { return k*(9-k)/2 + l; }

__global__ __launch_bounds__(NTHREADS)
void tfmptf_kernel(const float* __restrict__ in, float* __restrict__ out)
{
    extern __shared__ char smraw[];
    Smem& sm = *reinterpret_cast<Smem*>(smraw);
    const int tid = threadIdx.x;
    const int bid = blockIdx.x;          // bid = b*64 + d
    const int d = bid & 63;
    const int b = bid >> 6;
    const int warp = tid >> 5;

    // --- twiddles + input load + hist zero ---
    for (int j = tid; j < 3072; j += NTHREADS) {
        float sv, cv;
        sincospif(-(float)j * (1.0f/2048.0f), &sv, &cv); // angle = -2*pi*j/4096
        sm.tw[j] = make_float2(cv, sv);
    }
    const float* xin = in + ((long)b * TLEN) * 64 + d;
    for (int t = tid; t < TLEN; t += NTHREADS)
        sm.buf0[t] = make_float2(__ldg(&xin[(long)t * 64]), 0.0f);
    for (int i = tid; i < 16*36; i += NTHREADS) ((int*)sm.hist)[i] = 0;
    __syncthreads();

    // --- forward FFT: X in buf0 ---
    fft4096<false>(sm.buf0, sm.buf1, sm.tw, tid);

    // --- Y1 = X*(S0 + i*S1), save X and X_nyquist ---
    for (int j = tid; j < TLEN; j += NTHREADS) {
        float2 X = sm.buf0[j];
        sm.xsave[j] = X;
        if (j == 2048) sm.xnyq = X.x;
        float f = (float)((j < 2048) ? j : (j - 4096)) * (1.0f/4096.0f);
        float S0 = 0.5f * (gmask(f + 0.5f) + gmask(f - 0.5f));   // k=0 (c=-0.5)
        float S1 = 0.5f * (gmask(f - 0.3f) + gmask(f + 0.3f));   // k=1,4 merged
        sm.buf0[j] = make_float2(X.x*S0 - X.y*S1, X.x*S1 + X.y*S0);
    }
    __syncthreads();
    fft4096<true>(sm.buf0, sm.buf1, sm.tw, tid);
    for (int t = tid; t < TLEN; t += NTHREADS) {
        float2 z = sm.buf0[t];
        sm.modes[0][t] = z.x * (1.0f/4096.0f);
        sm.modes[1][t] = z.y * (1.0f/4096.0f);
    }
    __syncthreads();

    // --- Y2 = X*S2 ---
    for (int j = tid; j < TLEN; j += NTHREADS) {
        float2 X = sm.xsave[j];
        float f = (float)((j < 2048) ? j : (j - 4096)) * (1.0f/4096.0f);
        float S2 = 0.5f * (gmask(f - 0.1f) + gmask(f + 0.1f));   // k=2,3 merged
        sm.buf0[j] = make_float2(X.x*S2, X.y*S2);
    }
    __syncthreads();
    fft4096<true>(sm.buf0, sm.buf1, sm.tw, tid);
    for (int t = tid; t < TLEN; t += NTHREADS)
        sm.modes[2][t] = sm.buf0[t].x * (1.0f/4096.0f);
    __syncthreads();

    // --- Nyquist rank-1 corrections: true mode_k(t) = merged_g(t) +- eps_g*(-1)^t
    // D0 = (g(0)-g(1))/2, D1 = (g(0.2)-g(0.8))/2, D2 = (g(0.4)-g(0.6))/2
    const float xn = sm.xnyq * (1.0f/4096.0f);
    const float eg[3] = {
        0.5f * (1.0f            - expf(-12.5f))        * xn,
        0.5f * (expf(-0.5f)     - expf(-8.0f))         * xn,
        0.5f * (expf(-2.0f)     - expf(-4.5f))         * xn
    };
    // k -> (merged g, sign): k0:(0,+) k1:(1,+) k2:(2,+) k3:(2,-) k4:(1,-)
    const int kg[5]   = {0, 1, 2, 2, 1};
    const float ks[5] = {1.f, 1.f, 1.f, -1.f, -1.f};

    // --- sliding-window permutation transitions: 5 modes x 4093 transitions ---
    {
        const int W1 = 4093;
        const int w0 = tid * 8;
        const int wend = min(w0 + 8, W1);
        #pragma unroll
        for (int k = 0; k < 5; ++k) {
            const float* m = sm.modes[kg[k]];
            const float eps = ks[k] * eg[kg[k]];
            float a = m[w0]   + ((w0     & 1) ? -eps : eps);
            float bb = m[w0+1] + (((w0+1) & 1) ? -eps : eps);
            float cc = m[w0+2] + (((w0+2) & 1) ? -eps : eps);
            int prev = permid(a, bb, cc);
            for (int w = w0; w < wend; ++w) {
                a = bb; bb = cc;
                cc = m[w+3] + (((w+3) & 1) ? -eps : eps);
                int cur = permid(a, bb, cc);
                atomicAdd(&sm.hist[warp][prev*6 + cur], 1);
                prev = cur;
            }
        }
    }

    // --- correlation moments over e_k = mode_k^2 (5 sums + 15 products) ---
    float S[5]; float Q[15];
    #pragma unroll
    for (int i = 0; i < 5; ++i) S[i] = 0.f;
    #pragma unroll
    for (int i = 0; i < 15; ++i) Q[i] = 0.f;
    for (int t = tid; t < TLEN; t += NTHREADS) {
        float pe = (t & 1) ? -1.f : 1.f;
        float m0 = sm.modes[0][t], m1 = sm.modes[1][t], m2 = sm.modes[2][t];
        float v[5];
        v[0] = m0 + pe*eg[0];
        v[1] = m1 + pe*eg[1];
        v[2] = m2 + pe*eg[2];
        v[3] = m2 - pe*eg[2];
        v[4] = m1 - pe*eg[1];
        float e[5];
        #pragma unroll
        for (int k = 0; k < 5; ++k) e[k] = v[k]*v[k];
        #pragma unroll
        for (int k = 0; k < 5; ++k) {
            S[k] += e[k];
            #pragma unroll
            for (int l = k; l < 5; ++l)
                Q[qidx(k,l)] = fmaf(e[k], e[l], Q[qidx(k,l)]);
        }
    }
    {
        float vv[20];
        #pragma unroll
        for (int j = 0; j < 5; ++j)  vv[j]   = S[j];
        #pragma unroll
        for (int j = 0; j < 15; ++j) vv[5+j] = Q[j];
        #pragma unroll
        for (int j = 0; j < 20; ++j)
            #pragma unroll
            for (int off = 16; off; off >>= 1)
                vv[j] += __shfl_down_sync(0xffffffffu, vv[j], off);
        if ((tid & 31) == 0)
            #pragma unroll
            for (int j = 0; j < 20; ++j) sm.red[warp][j] = vv[j];
    }
    __syncthreads();   // hist atomics + red writes complete

    if (tid < 36) {
        int ctot = 0;
        #pragma unroll
        for (int w = 0; w < 16; ++w) ctot += sm.hist[w][tid];
        sm.cnt[tid] = ctot;
    }
    if (tid < 20) {
        float tot = 0.f;
        #pragma unroll
        for (int w = 0; w < 16; ++w) tot += sm.red[w][tid];
        sm.totals[tid] = tot;
    }
    __syncthreads();

    float* outbd = out + (long)bid * 46;
    if (tid < 36) {
        int p = tid / 6;
        int rs = 0;
        #pragma unroll
        for (int q = 0; q < 6; ++q) rs += sm.cnt[p*6 + q];
        float denom = rs ? (float)rs : 1.0f;
        outbd[tid] = (float)sm.cnt[tid] / denom;
    }
    if (tid == 0) {
        const float invT = 1.0f / 4096.0f;
        float cov[15];
        #pragma unroll
        for (int k = 0; k < 5; ++k)
            #pragma unroll
            for (int l = k; l < 5; ++l)
                cov[qidx(k,l)] = sm.totals[5 + qidx(k,l)]
                               - sm.totals[k]*sm.totals[l]*invT;
        float dstd[5];
        #pragma unroll
        for (int k = 0; k < 5; ++k) dstd[k] = sqrtf(fmaxf(cov[qidx(k,k)], 0.f));
        // upper-triangle pair order: (0,1)(0,2)(0,3)(0,4)(1,2)(1,3)(1,4)(2,3)(2,4)(3,4)
        int oi = 36;
        #pragma unroll
        for (int k = 0; k < 5; ++k) {
            #pragma unroll
            for (int l = k+1; l < 5; ++l) {
                float den = dstd[k] * dstd[l];
                float r = (den > 0.f) ? cov[qidx(k,l)] / den : 0.f;
                r = fminf(1.f, fmaxf(-1.f, r));
                outbd[oi++] = r;
            }
        }
    }
}

extern "C" void kernel_launch(void* const* d_in, const int* in_sizes, int n_in,
                              void* d_out, int out_size)
{
    (void)in_sizes; (void)n_in; (void)out_size;
    const float* in = (const float*)d_in[0];
    float* out = (float*)d_out;
    cudaFuncSetAttribute(tfmptf_kernel, cudaFuncAttributeMaxDynamicSharedMemorySize,
                         (int)sizeof(Smem));
    tfmptf_kernel<<<1024, NTHREADS, sizeof(Smem)>>>(in, out);
}